// round 14
// baseline (speedup 1.0000x reference)
#include <cuda_runtime.h>
#include <cuda_fp16.h>
#include <math.h>
#include <stdint.h>

#define Bdim 32
#define Sdim 2048
#define ENC  1024
#define DEC  1024
#define WTOT 2048
#define NEGV (-1e10f)

// ---------------- scratch ---------------------------------------------------
__device__ uint4 g_encH4[(size_t)Bdim * Sdim * ENC / 8]; // enc as fp16 [m][k]
__device__ uint4 g_weH4[DEC * ENC / 8];                  // w_e as fp16 [n][k]
__device__ float g_hpb[Bdim * DEC];                      // h_proj + bias
__device__ float g_part[(size_t)Bdim * Sdim * 8];        // per-(m, ntile) partials
__device__ float g_ctx_part[16 * Bdim * ENC];            // split ctx partials

// ---------------- helpers ----------------------------------------------------
__device__ __forceinline__ uint32_t smem_u32(const void* p) {
    uint32_t a;
    asm("{ .reg .u64 t; cvta.to.shared.u64 t, %1; cvt.u32.u64 %0, t; }"
        : "=r"(a) : "l"(p));
    return a;
}
__device__ __forceinline__ uint32_t h2pack(float x, float y) {
    __half2 h = __floats2half2_rn(x, y);
    return *(uint32_t*)&h;
}
__device__ __forceinline__ void mma_f16(float* d, uint32_t a0, uint32_t a1,
                                        uint32_t a2, uint32_t a3,
                                        uint32_t b0, uint32_t b1) {
    asm volatile(
        "mma.sync.aligned.m16n8k16.row.col.f32.f16.f16.f32 "
        "{%0,%1,%2,%3}, {%4,%5,%6,%7}, {%8,%9}, {%0,%1,%2,%3};"
        : "+f"(d[0]), "+f"(d[1]), "+f"(d[2]), "+f"(d[3])
        : "r"(a0), "r"(a1), "r"(a2), "r"(a3), "r"(b0), "r"(b1));
}
#define LDSM4(r0, r1, r2, r3, a) \
    asm volatile("ldmatrix.sync.aligned.m8n8.x4.shared.b16 {%0,%1,%2,%3}, [%4];" \
                 : "=r"(r0), "=r"(r1), "=r"(r2), "=r"(r3) : "r"(a))

// ---------------- prep: enc conversion (blocks 0..4095) + hproj (4096..4223)
// Conversion blocks stream enc fp32 -> fp16 (DRAM-bound, SMs mostly idle);
// hproj blocks (8 k-rows each, coalesced) run concurrently in the leftover
// issue slots. w_e fp16 conversion rides with hproj.
__global__ __launch_bounds__(256) void prep_kernel(
    const float* __restrict__ enc,
    const float* __restrict__ hidden,
    const float* __restrict__ attn_w,
    const float* __restrict__ attn_b) {
    __shared__ float ws8[8 * DEC];              // 32 KB (hproj blocks only)
    int tid = threadIdx.x;

    if (blockIdx.x < 4096) {
        size_t n8 = (size_t)Bdim * Sdim * ENC / 8;
        size_t stride = (size_t)4096 * 256;
        for (size_t i = (size_t)blockIdx.x * 256 + tid; i < n8; i += stride) {
            float4 f0 = ((const float4*)enc)[2 * i];
            float4 f1 = ((const float4*)enc)[2 * i + 1];
            uint4 o;
            o.x = h2pack(f0.x, f0.y); o.y = h2pack(f0.z, f0.w);
            o.z = h2pack(f1.x, f1.y); o.w = h2pack(f1.z, f1.w);
            g_encH4[i] = o;
        }
        return;
    }

    int kb = (blockIdx.x - 4096) * 8;
    // stage w_h rows (8 x 1024 floats) via float4, coalesced
#pragma unroll
    for (int t = 0; t < 8; ++t) {
        int u = t * 256 + tid;
        int r = u >> 8, c = u & 255;
        ((float4*)ws8)[r * 256 + c] =
            ((const float4*)(attn_w + (size_t)(kb + r) * WTOT))[c];
    }
    // convert w_e rows kb..kb+7, coalesced
#pragma unroll
    for (int t = 0; t < 4; ++t) {
        int u = t * 256 + tid;
        int r = u >> 7, c = u & 127;
        const float* src = attn_w + (size_t)(kb + r) * WTOT + DEC + c * 8;
        float4 f0 = ((const float4*)src)[0];
        float4 f1 = ((const float4*)src)[1];
        uint4 o;
        o.x = h2pack(f0.x, f0.y); o.y = h2pack(f0.z, f0.w);
        o.z = h2pack(f1.x, f1.y); o.w = h2pack(f1.z, f1.w);
        g_weH4[(kb + r) * 128 + c] = o;
    }
    __syncthreads();

    int b = tid >> 3, l = tid & 7;
    const float4* h4 = (const float4*)(hidden + (size_t)b * DEC);
    const float4* w4 = (const float4*)ws8;
    float p[8];
#pragma unroll
    for (int kk = 0; kk < 8; ++kk) p[kk] = 0.f;
    for (int j = l; j < 256; j += 8) {
        float4 hv = h4[j];
#pragma unroll
        for (int kk = 0; kk < 8; ++kk) {
            float4 wv = w4[kk * 256 + j];
            p[kk] += hv.x * wv.x + hv.y * wv.y + hv.z * wv.z + hv.w * wv.w;
        }
    }
#pragma unroll
    for (int kk = 0; kk < 8; ++kk) {
        p[kk] += __shfl_down_sync(0xffffffffu, p[kk], 4, 8);
        p[kk] += __shfl_down_sync(0xffffffffu, p[kk], 2, 8);
        p[kk] += __shfl_down_sync(0xffffffffu, p[kk], 1, 8);
    }
    if (l == 0) {
#pragma unroll
        for (int kk = 0; kk < 8; ++kk)
            g_hpb[b * DEC + kb + kk] = p[kk] + attn_b[kb + kk];
    }
}

// ---------------- energy GEMM: fp16 mma.sync, frag-pipelined (R9 best) ------
#define NCHUNK 32
#define A_STG_B 10240            // 128 rows * 80B
#define B_STG_B 10240
#define STG_B   (A_STG_B + B_STG_B)
#define NSTAGE  5
#define DYN_SMEM (NSTAGE * STG_B)

__device__ __forceinline__ void issue_chunk(uint32_t sbase, int stage, int chunk,
                                            int m0, int n0, int tid) {
    uint32_t sb = sbase + stage * STG_B;
    int k0 = chunk * 32;
    const __half* encH = (const __half*)g_encH4;
    const __half* weH  = (const __half*)g_weH4;
#pragma unroll
    for (int t = 0; t < 8; ++t) {
        int u = t * 128 + tid;                  // 16B units: A 512, B 512
        const __half* g;
        uint32_t so;
        if (u < 512) {
            int r = u >> 2, seg = u & 3;
            so = (uint32_t)(r * 80 + seg * 16);
            g = encH + (size_t)(m0 + r) * ENC + k0 + seg * 8;
        } else {
            int v = u - 512;
            int r = v >> 2, seg = v & 3;
            so = (uint32_t)(A_STG_B + r * 80 + seg * 16);
            g = weH + (size_t)(n0 + r) * ENC + k0 + seg * 8;
        }
        asm volatile("cp.async.cg.shared.global [%0], [%1], 16;"
                     :: "r"(sb + so), "l"(g));
    }
    asm volatile("cp.async.commit_group;" ::: "memory");
}

struct Frag { uint32_t r[4]; };
struct FragSet { Frag a[4]; Frag b[4]; };

__device__ __forceinline__ void load_frags(FragSet& f, uint32_t sb,
                                           uint32_t aBase, uint32_t bBase,
                                           uint32_t koff) {
#pragma unroll
    for (int p = 0; p < 4; ++p)
        LDSM4(f.a[p].r[0], f.a[p].r[1], f.a[p].r[2], f.a[p].r[3],
              sb + aBase + p * 1280 + koff);
#pragma unroll
    for (int p = 0; p < 4; ++p)
        LDSM4(f.b[p].r[0], f.b[p].r[1], f.b[p].r[2], f.b[p].r[3],
              sb + bBase + p * 1280 + koff);
}

__device__ __forceinline__ void mma_set(float acc[4][8][4], const FragSet& f) {
#pragma unroll
    for (int mi = 0; mi < 4; ++mi)
#pragma unroll
        for (int p = 0; p < 4; ++p) {
            mma_f16(acc[mi][2 * p],     f.a[mi].r[0], f.a[mi].r[1],
                    f.a[mi].r[2], f.a[mi].r[3], f.b[p].r[0], f.b[p].r[1]);
            mma_f16(acc[mi][2 * p + 1], f.a[mi].r[0], f.a[mi].r[1],
                    f.a[mi].r[2], f.a[mi].r[3], f.b[p].r[2], f.b[p].r[3]);
        }
}

__global__ void __launch_bounds__(128, 2) energy_kernel(const float* __restrict__ v_w) {
    extern __shared__ uint32_t sm[];
    __shared__ float red[128][2];
    uint32_t sbase = smem_u32(sm);

    int tid = threadIdx.x;
    int wid = tid >> 5, lane = tid & 31;
    int wm = wid >> 1, wn = wid & 1;            // 2x2 warp grid
    int ty = lane >> 2, tx = lane & 3;
    int nt = blockIdx.x, mt = blockIdx.y;
    int m0 = mt * 128, n0 = nt * 128;
    int bb = m0 >> 11;

    int aRow = wm * 64 + (lane & 7) + (((lane >> 3) & 1) << 3);
    uint32_t aBase = (uint32_t)(aRow * 80 + ((lane >> 4) << 4));
    int bRow = wn * 64 + (lane & 7) + ((lane >> 4) << 3);
    uint32_t bBase = (uint32_t)(A_STG_B + bRow * 80 + (((lane >> 3) & 1) << 4));

    float acc[4][8][4];
#pragma unroll
    for (int mi = 0; mi < 4; ++mi)
#pragma unroll
        for (int ni = 0; ni < 8; ++ni)
#pragma unroll
            for (int c = 0; c < 4; ++c) acc[mi][ni][c] = 0.f;

    issue_chunk(sbase, 0, 0, m0, n0, tid);
    issue_chunk(sbase, 1, 1, m0, n0, tid);
    issue_chunk(sbase, 2, 2, m0, n0, tid);
    issue_chunk(sbase, 3, 3, m0, n0, tid);

    FragSet cur, nxt;
    asm volatile("cp.async.wait_group 3;" ::: "memory");
    __syncthreads();
    load_frags(cur, sbase, aBase, bBase, 0);

    for (int i = 0; i < NCHUNK; ++i) {
        if (i < 29)      asm volatile("cp.async.wait_group 2;" ::: "memory");
        else if (i == 29) asm volatile("cp.async.wait_group 1;" ::: "memory");
        else              asm volatile("cp.async.wait_group 0;" ::: "memory");
        __syncthreads();
        if (i + 4 < NCHUNK)
            issue_chunk(sbase, (i + 4) % NSTAGE, i + 4, m0, n0, tid);

        uint32_t sb  = sbase + (i % NSTAGE) * STG_B;
        uint32_t sbn = sbase + ((i + 1) % NSTAGE) * STG_B;

        load_frags(nxt, sb, aBase, bBase, 32);
        mma_set(acc, cur);
        if (i + 1 < NCHUNK) load_frags(cur, sbn, aBase, bBase, 0);
        mma_set(acc, nxt);
    }

    // Epilogue: tanh + v_w partial reduction over this block's 128 cols.
    int colbase = n0 + wn * 64 + tx * 2;
    int hb = bb * DEC;
    float pr[4][2];
#pragma unroll
    for (int mi = 0; mi < 4; ++mi) { pr[mi][0] = 0.f; pr[mi][1] = 0.f; }
#pragma unroll
    for (int ni = 0; ni < 8; ++ni) {
        int c0 = colbase + ni * 8;
        float hp0 = g_hpb[hb + c0],  hp1 = g_hpb[hb + c0 + 1];
        float vw0 = v_w[c0],         vw1 = v_w[c0 + 1];
#pragma unroll
        for (int mi = 0; mi < 4; ++mi) {
            pr[mi][0] += tanhf(acc[mi][ni][0] + hp0) * vw0
                       + tanhf(acc[mi][ni][1] + hp1) * vw1;
            pr[mi][1] += tanhf(acc[mi][ni][2] + hp0) * vw0
                       + tanhf(acc[mi][ni][3] + hp1) * vw1;
        }
    }
#pragma unroll
    for (int mi = 0; mi < 4; ++mi)
#pragma unroll
        for (int h = 0; h < 2; ++h) {
            float p = pr[mi][h];
            p += __shfl_xor_sync(0xffffffffu, p, 1);
            p += __shfl_xor_sync(0xffffffffu, p, 2);
            if (tx == 0) red[wm * 64 + mi * 16 + h * 8 + ty][wn] = p;
        }
    __syncthreads();
    g_part[((size_t)(m0 + tid)) * 8 + nt] = red[tid][0] + red[tid][1];
}

// ---------------- masked softmax (512 threads, sums 8 partials) -------------
__global__ void softmax_kernel(const int* __restrict__ mask, float* __restrict__ out) {
    int b = blockIdx.x;
    __shared__ float sh[Sdim];
    __shared__ float wr[16];
    int tid = threadIdx.x;  // 512

    float lmax = -1e30f;
    for (int s = tid; s < Sdim; s += 512) {
        float v;
        if (mask[b * Sdim + s] == 0) v = NEGV;
        else {
            const float4* pp = (const float4*)(g_part + ((size_t)(b * Sdim + s)) * 8);
            float4 p0 = pp[0], p1 = pp[1];
            v = ((p0.x + p0.y) + (p0.z + p0.w)) + ((p1.x + p1.y) + (p1.z + p1.w));
        }
        sh[s] = v;
        lmax = fmaxf(lmax, v);
    }
#pragma unroll
    for (int o = 16; o; o >>= 1) lmax = fmaxf(lmax, __shfl_xor_sync(~0u, lmax, o));
    if ((tid & 31) == 0) wr[tid >> 5] = lmax;
    __syncthreads();
    if (tid < 32) {
        float v = (tid < 16) ? wr[tid] : -1e30f;
#pragma unroll
        for (int o = 8; o; o >>= 1) v = fmaxf(v, __shfl_xor_sync(~0u, v, o));
        if (tid == 0) wr[0] = v;
    }
    __syncthreads();
    float gmax = wr[0];

    float lsum = 0.f;
    for (int s = tid; s < Sdim; s += 512) {
        float e = expf(sh[s] - gmax);
        sh[s] = e;
        lsum += e;
    }
    __syncthreads();
#pragma unroll
    for (int o = 16; o; o >>= 1) lsum += __shfl_xor_sync(~0u, lsum, o);
    if ((tid & 31) == 0) wr[tid >> 5] = lsum;
    __syncthreads();
    if (tid < 32) {
        float v = (tid < 16) ? wr[tid] : 0.f;
#pragma unroll
        for (int o = 8; o; o >>= 1) v += __shfl_xor_sync(~0u, v, o);
        if (tid == 0) wr[0] = v;
    }
    __syncthreads();
    float inv = 1.f / wr[0];
    float* w = out + Bdim * DEC;
    for (int s = tid; s < Sdim; s += 512) w[b * Sdim + s] = sh[s] * inv;
}

// ---------------- context: uint4 loads, row-parity split (z2 = 16 slots) ----
// grid (Bdim, 8), 256 threads. seg = tid&127 owns 8 consecutive halves
// (one uint4 per row); parity = tid>>7 streams odd/even rows of the z-slice.
// Partials land in z2 = 2z+parity; reduce sums 16.
__global__ __launch_bounds__(256) void ctx_part_kernel(const float* __restrict__ w) {
    int seg = threadIdx.x & 127;
    int parity = threadIdx.x >> 7;
    int b = blockIdx.x, z = blockIdx.y;
    const uint4* ep = g_encH4 + ((size_t)b * Sdim + z * 256) * 128 + seg;
    const float* wp = w + b * Sdim + z * 256;

    float a0 = 0.f, a1 = 0.f, a2 = 0.f, a3 = 0.f;
    float a4 = 0.f, a5 = 0.f, a6 = 0.f, a7 = 0.f;
    for (int s0 = 0; s0 < 256; s0 += 16) {
#pragma unroll
        for (int u = 0; u < 8; ++u) {
            int r = s0 + u * 2 + parity;
            uint4 v = ep[(size_t)r * 128];
            float wv = wp[r];
            float2 f0 = __half22float2(*(__half2*)&v.x);
            float2 f1 = __half22float2(*(__half2*)&v.y);
            float2 f2 = __half22float2(*(__half2*)&v.z);
            float2 f3 = __half22float2(*(__half2*)&v.w);
            a0 += wv * f0.x; a1 += wv * f0.y;
            a2 += wv * f1.x; a3 += wv * f1.y;
            a4 += wv * f2.x; a5 += wv * f2.y;
            a6 += wv * f3.x; a7 += wv * f3.y;
        }
    }
    int z2 = z * 2 + parity;
    float* dst = g_ctx_part + (((size_t)z2 * Bdim + b) << 10) + seg * 8;
    ((float4*)dst)[0] = make_float4(a0, a1, a2, a3);
    ((float4*)dst)[1] = make_float4(a4, a5, a6, a7);
}
__global__ void ctx_reduce_kernel(float* __restrict__ out) {
    int id = blockIdx.x * 256 + threadIdx.x;
    float s = 0.f;
#pragma unroll
    for (int z = 0; z < 16; ++z) s += g_ctx_part[(z << 15) + id];
    out[id] = s;
}

// ---------------------------------------------------------------------------
extern "C" void kernel_launch(void* const* d_in, const int* in_sizes, int n_in,
                              void* d_out, int out_size) {
    const float* hidden = (const float*)d_in[0];
    const float* enc    = (const float*)d_in[1];
    const int*   mask   = (const int*)d_in[2];
    const float* attn_w = (const float*)d_in[3];
    const float* attn_b = (const float*)d_in[4];
    const float* v_w    = (const float*)d_in[5];
    float* out = (float*)d_out;   // [context(32x1024), weights(32x2048)]

    cudaFuncSetAttribute(energy_kernel,
                         cudaFuncAttributeMaxDynamicSharedMemorySize, DYN_SMEM);

    prep_kernel<<<4224, 256>>>(enc, hidden, attn_w, attn_b);
    energy_kernel<<<dim3(8, 512), 128, DYN_SMEM>>>(v_w);
    softmax_kernel<<<Bdim, 512>>>(mask, out);
    ctx_part_kernel<<<dim3(Bdim, 8), 256>>>(out + Bdim * DEC);
    ctx_reduce_kernel<<<128, 256>>>(out);
}

// round 15
// speedup vs baseline: 1.0475x; 1.0475x over previous
#include <cuda_runtime.h>
#include <cuda_fp16.h>
#include <math.h>
#include <stdint.h>

#define Bdim 32
#define Sdim 2048
#define ENC  1024
#define DEC  1024
#define WTOT 2048
#define NEGV (-1e10f)

// ---------------- scratch ---------------------------------------------------
__device__ uint4 g_encH4[(size_t)Bdim * Sdim * ENC / 8]; // enc as fp16 [m][k]
__device__ uint4 g_weH4[DEC * ENC / 8];                  // w_e as fp16 [n][k]
__device__ float g_hpb[Bdim * DEC];                      // h_proj + bias
__device__ float g_part[(size_t)Bdim * Sdim * 8];        // per-(m, ntile) partials
__device__ float g_ctx_part[32 * Bdim * ENC];            // split ctx partials (4MB)

// ---------------- helpers ----------------------------------------------------
__device__ __forceinline__ uint32_t smem_u32(const void* p) {
    uint32_t a;
    asm("{ .reg .u64 t; cvta.to.shared.u64 t, %1; cvt.u32.u64 %0, t; }"
        : "=r"(a) : "l"(p));
    return a;
}
__device__ __forceinline__ uint32_t h2pack(float x, float y) {
    __half2 h = __floats2half2_rn(x, y);
    return *(uint32_t*)&h;
}
__device__ __forceinline__ void mma_f16(float* d, uint32_t a0, uint32_t a1,
                                        uint32_t a2, uint32_t a3,
                                        uint32_t b0, uint32_t b1) {
    asm volatile(
        "mma.sync.aligned.m16n8k16.row.col.f32.f16.f16.f32 "
        "{%0,%1,%2,%3}, {%4,%5,%6,%7}, {%8,%9}, {%0,%1,%2,%3};"
        : "+f"(d[0]), "+f"(d[1]), "+f"(d[2]), "+f"(d[3])
        : "r"(a0), "r"(a1), "r"(a2), "r"(a3), "r"(b0), "r"(b1));
}
#define LDSM4(r0, r1, r2, r3, a) \
    asm volatile("ldmatrix.sync.aligned.m8n8.x4.shared.b16 {%0,%1,%2,%3}, [%4];" \
                 : "=r"(r0), "=r"(r1), "=r"(r2), "=r"(r3) : "r"(a))

// ---------------- enc fp32 -> fp16 ------------------------------------------
__global__ void enc_to_half(const float* __restrict__ enc) {
    size_t n8 = (size_t)Bdim * Sdim * ENC / 8;
    size_t stride = (size_t)gridDim.x * blockDim.x;
    for (size_t i = (size_t)blockIdx.x * blockDim.x + threadIdx.x; i < n8; i += stride) {
        float4 f0 = ((const float4*)enc)[2 * i];
        float4 f1 = ((const float4*)enc)[2 * i + 1];
        uint4 o;
        o.x = h2pack(f0.x, f0.y); o.y = h2pack(f0.z, f0.w);
        o.z = h2pack(f1.x, f1.y); o.w = h2pack(f1.z, f1.w);
        g_encH4[i] = o;
    }
}

// ---------------- h_proj + bias (8 k-rows/block, coalesced) + w_e conv ------
__global__ __launch_bounds__(256) void hproj_kernel(
    const float* __restrict__ hidden,
    const float* __restrict__ attn_w,
    const float* __restrict__ attn_b) {
    __shared__ float ws8[8 * DEC];              // 32 KB
    int tid = threadIdx.x;
    int kb = blockIdx.x * 8;

#pragma unroll
    for (int t = 0; t < 8; ++t) {
        int u = t * 256 + tid;
        int r = u >> 8, c = u & 255;
        ((float4*)ws8)[r * 256 + c] =
            ((const float4*)(attn_w + (size_t)(kb + r) * WTOT))[c];
    }
#pragma unroll
    for (int t = 0; t < 4; ++t) {
        int u = t * 256 + tid;
        int r = u >> 7, c = u & 127;
        const float* src = attn_w + (size_t)(kb + r) * WTOT + DEC + c * 8;
        float4 f0 = ((const float4*)src)[0];
        float4 f1 = ((const float4*)src)[1];
        uint4 o;
        o.x = h2pack(f0.x, f0.y); o.y = h2pack(f0.z, f0.w);
        o.z = h2pack(f1.x, f1.y); o.w = h2pack(f1.z, f1.w);
        g_weH4[(kb + r) * 128 + c] = o;
    }
    __syncthreads();

    int b = tid >> 3, l = tid & 7;
    const float4* h4 = (const float4*)(hidden + (size_t)b * DEC);
    const float4* w4 = (const float4*)ws8;
    float p[8];
#pragma unroll
    for (int kk = 0; kk < 8; ++kk) p[kk] = 0.f;
    for (int j = l; j < 256; j += 8) {
        float4 hv = h4[j];
#pragma unroll
        for (int kk = 0; kk < 8; ++kk) {
            float4 wv = w4[kk * 256 + j];
            p[kk] += hv.x * wv.x + hv.y * wv.y + hv.z * wv.z + hv.w * wv.w;
        }
    }
#pragma unroll
    for (int kk = 0; kk < 8; ++kk) {
        p[kk] += __shfl_down_sync(0xffffffffu, p[kk], 4, 8);
        p[kk] += __shfl_down_sync(0xffffffffu, p[kk], 2, 8);
        p[kk] += __shfl_down_sync(0xffffffffu, p[kk], 1, 8);
    }
    if (l == 0) {
#pragma unroll
        for (int kk = 0; kk < 8; ++kk)
            g_hpb[b * DEC + kb + kk] = p[kk] + attn_b[kb + kk];
    }
}

// ---------------- energy GEMM: fp16 mma.sync, frag-pipelined (R9 best) ------
#define NCHUNK 32
#define A_STG_B 10240            // 128 rows * 80B
#define B_STG_B 10240
#define STG_B   (A_STG_B + B_STG_B)
#define NSTAGE  5
#define DYN_SMEM (NSTAGE * STG_B)

__device__ __forceinline__ void issue_chunk(uint32_t sbase, int stage, int chunk,
                                            int m0, int n0, int tid) {
    uint32_t sb = sbase + stage * STG_B;
    int k0 = chunk * 32;
    const __half* encH = (const __half*)g_encH4;
    const __half* weH  = (const __half*)g_weH4;
#pragma unroll
    for (int t = 0; t < 8; ++t) {
        int u = t * 128 + tid;                  // 16B units: A 512, B 512
        const __half* g;
        uint32_t so;
        if (u < 512) {
            int r = u >> 2, seg = u & 3;
            so = (uint32_t)(r * 80 + seg * 16);
            g = encH + (size_t)(m0 + r) * ENC + k0 + seg * 8;
        } else {
            int v = u - 512;
            int r = v >> 2, seg = v & 3;
            so = (uint32_t)(A_STG_B + r * 80 + seg * 16);
            g = weH + (size_t)(n0 + r) * ENC + k0 + seg * 8;
        }
        asm volatile("cp.async.cg.shared.global [%0], [%1], 16;"
                     :: "r"(sb + so), "l"(g));
    }
    asm volatile("cp.async.commit_group;" ::: "memory");
}

struct Frag { uint32_t r[4]; };
struct FragSet { Frag a[4]; Frag b[4]; };

__device__ __forceinline__ void load_frags(FragSet& f, uint32_t sb,
                                           uint32_t aBase, uint32_t bBase,
                                           uint32_t koff) {
#pragma unroll
    for (int p = 0; p < 4; ++p)
        LDSM4(f.a[p].r[0], f.a[p].r[1], f.a[p].r[2], f.a[p].r[3],
              sb + aBase + p * 1280 + koff);
#pragma unroll
    for (int p = 0; p < 4; ++p)
        LDSM4(f.b[p].r[0], f.b[p].r[1], f.b[p].r[2], f.b[p].r[3],
              sb + bBase + p * 1280 + koff);
}

__device__ __forceinline__ void mma_set(float acc[4][8][4], const FragSet& f) {
#pragma unroll
    for (int mi = 0; mi < 4; ++mi)
#pragma unroll
        for (int p = 0; p < 4; ++p) {
            mma_f16(acc[mi][2 * p],     f.a[mi].r[0], f.a[mi].r[1],
                    f.a[mi].r[2], f.a[mi].r[3], f.b[p].r[0], f.b[p].r[1]);
            mma_f16(acc[mi][2 * p + 1], f.a[mi].r[0], f.a[mi].r[1],
                    f.a[mi].r[2], f.a[mi].r[3], f.b[p].r[2], f.b[p].r[3]);
        }
}

__global__ void __launch_bounds__(128, 2) energy_kernel(const float* __restrict__ v_w) {
    extern __shared__ uint32_t sm[];
    __shared__ float red[128][2];
    uint32_t sbase = smem_u32(sm);

    int tid = threadIdx.x;
    int wid = tid >> 5, lane = tid & 31;
    int wm = wid >> 1, wn = wid & 1;            // 2x2 warp grid
    int ty = lane >> 2, tx = lane & 3;
    int nt = blockIdx.x, mt = blockIdx.y;
    int m0 = mt * 128, n0 = nt * 128;
    int bb = m0 >> 11;

    int aRow = wm * 64 + (lane & 7) + (((lane >> 3) & 1) << 3);
    uint32_t aBase = (uint32_t)(aRow * 80 + ((lane >> 4) << 4));
    int bRow = wn * 64 + (lane & 7) + ((lane >> 4) << 3);
    uint32_t bBase = (uint32_t)(A_STG_B + bRow * 80 + (((lane >> 3) & 1) << 4));

    float acc[4][8][4];
#pragma unroll
    for (int mi = 0; mi < 4; ++mi)
#pragma unroll
        for (int ni = 0; ni < 8; ++ni)
#pragma unroll
            for (int c = 0; c < 4; ++c) acc[mi][ni][c] = 0.f;

    issue_chunk(sbase, 0, 0, m0, n0, tid);
    issue_chunk(sbase, 1, 1, m0, n0, tid);
    issue_chunk(sbase, 2, 2, m0, n0, tid);
    issue_chunk(sbase, 3, 3, m0, n0, tid);

    FragSet cur, nxt;
    asm volatile("cp.async.wait_group 3;" ::: "memory");
    __syncthreads();
    load_frags(cur, sbase, aBase, bBase, 0);

    for (int i = 0; i < NCHUNK; ++i) {
        if (i < 29)      asm volatile("cp.async.wait_group 2;" ::: "memory");
        else if (i == 29) asm volatile("cp.async.wait_group 1;" ::: "memory");
        else              asm volatile("cp.async.wait_group 0;" ::: "memory");
        __syncthreads();
        if (i + 4 < NCHUNK)
            issue_chunk(sbase, (i + 4) % NSTAGE, i + 4, m0, n0, tid);

        uint32_t sb  = sbase + (i % NSTAGE) * STG_B;
        uint32_t sbn = sbase + ((i + 1) % NSTAGE) * STG_B;

        load_frags(nxt, sb, aBase, bBase, 32);
        mma_set(acc, cur);
        if (i + 1 < NCHUNK) load_frags(cur, sbn, aBase, bBase, 0);
        mma_set(acc, nxt);
    }

    // Epilogue: tanh + v_w partial reduction over this block's 128 cols.
    int colbase = n0 + wn * 64 + tx * 2;
    int hb = bb * DEC;
    float pr[4][2];
#pragma unroll
    for (int mi = 0; mi < 4; ++mi) { pr[mi][0] = 0.f; pr[mi][1] = 0.f; }
#pragma unroll
    for (int ni = 0; ni < 8; ++ni) {
        int c0 = colbase + ni * 8;
        float hp0 = g_hpb[hb + c0],  hp1 = g_hpb[hb + c0 + 1];
        float vw0 = v_w[c0],         vw1 = v_w[c0 + 1];
#pragma unroll
        for (int mi = 0; mi < 4; ++mi) {
            pr[mi][0] += tanhf(acc[mi][ni][0] + hp0) * vw0
                       + tanhf(acc[mi][ni][1] + hp1) * vw1;
            pr[mi][1] += tanhf(acc[mi][ni][2] + hp0) * vw0
                       + tanhf(acc[mi][ni][3] + hp1) * vw1;
        }
    }
#pragma unroll
    for (int mi = 0; mi < 4; ++mi)
#pragma unroll
        for (int h = 0; h < 2; ++h) {
            float p = pr[mi][h];
            p += __shfl_xor_sync(0xffffffffu, p, 1);
            p += __shfl_xor_sync(0xffffffffu, p, 2);
            if (tx == 0) red[wm * 64 + mi * 16 + h * 8 + ty][wn] = p;
        }
    __syncthreads();
    g_part[((size_t)(m0 + tid)) * 8 + nt] = red[tid][0] + red[tid][1];
}

// ---------------- masked softmax (512 threads, sums 8 partials) -------------
__global__ void softmax_kernel(const int* __restrict__ mask, float* __restrict__ out) {
    int b = blockIdx.x;
    __shared__ float sh[Sdim];
    __shared__ float wr[16];
    int tid = threadIdx.x;  // 512

    float lmax = -1e30f;
    for (int s = tid; s < Sdim; s += 512) {
        float v;
        if (mask[b * Sdim + s] == 0) v = NEGV;
        else {
            const float4* pp = (const float4*)(g_part + ((size_t)(b * Sdim + s)) * 8);
            float4 p0 = pp[0], p1 = pp[1];
            v = ((p0.x + p0.y) + (p0.z + p0.w)) + ((p1.x + p1.y) + (p1.z + p1.w));
        }
        sh[s] = v;
        lmax = fmaxf(lmax, v);
    }
#pragma unroll
    for (int o = 16; o; o >>= 1) lmax = fmaxf(lmax, __shfl_xor_sync(~0u, lmax, o));
    if ((tid & 31) == 0) wr[tid >> 5] = lmax;
    __syncthreads();
    if (tid < 32) {
        float v = (tid < 16) ? wr[tid] : -1e30f;
#pragma unroll
        for (int o = 8; o; o >>= 1) v = fmaxf(v, __shfl_xor_sync(~0u, v, o));
        if (tid == 0) wr[0] = v;
    }
    __syncthreads();
    float gmax = wr[0];

    float lsum = 0.f;
    for (int s = tid; s < Sdim; s += 512) {
        float e = expf(sh[s] - gmax);
        sh[s] = e;
        lsum += e;
    }
    __syncthreads();
#pragma unroll
    for (int o = 16; o; o >>= 1) lsum += __shfl_xor_sync(~0u, lsum, o);
    if ((tid & 31) == 0) wr[tid >> 5] = lsum;
    __syncthreads();
    if (tid < 32) {
        float v = (tid < 16) ? wr[tid] : 0.f;
#pragma unroll
        for (int o = 8; o; o >>= 1) v += __shfl_xor_sync(~0u, v, o);
        if (tid == 0) wr[0] = v;
    }
    __syncthreads();
    float inv = 1.f / wr[0];
    float* w = out + Bdim * DEC;
    for (int s = tid; s < Sdim; s += 512) w[b * Sdim + s] = sh[s] * inv;
}

// ---------------- context: uint4 loads, 512 blocks, parity split ------------
// grid (Bdim, 16), 256 threads. z-slice = 128 rows; seg = tid&127 owns one
// uint4 (8 halves) per row; parity = tid>>7 streams 64 parity-interleaved
// rows. Partials land in z2 = 2z+parity (32 slots); reduce sums 32.
__global__ __launch_bounds__(256) void ctx_part_kernel(const float* __restrict__ w) {
    int seg = threadIdx.x & 127;
    int parity = threadIdx.x >> 7;
    int b = blockIdx.x, z = blockIdx.y;
    const uint4* ep = g_encH4 + ((size_t)b * Sdim + z * 128) * 128 + seg;
    const float* wp = w + b * Sdim + z * 128;

    float a0 = 0.f, a1 = 0.f, a2 = 0.f, a3 = 0.f;
    float a4 = 0.f, a5 = 0.f, a6 = 0.f, a7 = 0.f;
    for (int s0 = 0; s0 < 128; s0 += 16) {
#pragma unroll
        for (int u = 0; u < 8; ++u) {
            int r = s0 + u * 2 + parity;
            uint4 v = ep[(size_t)r * 128];
            float wv = wp[r];
            float2 f0 = __half22float2(*(__half2*)&v.x);
            float2 f1 = __half22float2(*(__half2*)&v.y);
            float2 f2 = __half22float2(*(__half2*)&v.z);
            float2 f3 = __half22float2(*(__half2*)&v.w);
            a0 += wv * f0.x; a1 += wv * f0.y;
            a2 += wv * f1.x; a3 += wv * f1.y;
            a4 += wv * f2.x; a5 += wv * f2.y;
            a6 += wv * f3.x; a7 += wv * f3.y;
        }
    }
    int z2 = z * 2 + parity;
    float* dst = g_ctx_part + (((size_t)z2 * Bdim + b) << 10) + seg * 8;
    ((float4*)dst)[0] = make_float4(a0, a1, a2, a3);
    ((float4*)dst)[1] = make_float4(a4, a5, a6, a7);
}
__global__ void ctx_reduce_kernel(float* __restrict__ out) {
    int id = blockIdx.x * 256 + threadIdx.x;
    float s = 0.f;
#pragma unroll
    for (int z = 0; z < 32; ++z) s += g_ctx_part[(z << 15) + id];
    out[id] = s;
}

// ---------------------------------------------------------------------------
extern "C" void kernel_launch(void* const* d_in, const int* in_sizes, int n_in,
                              void* d_out, int out_size) {
    const float* hidden = (const float*)d_in[0];
    const float* enc    = (const float*)d_in[1];
    const int*   mask   = (const int*)d_in[2];
    const float* attn_w = (const float*)d_in[3];
    const float* attn_b = (const float*)d_in[4];
    const float* v_w    = (const float*)d_in[5];
    float* out = (float*)d_out;   // [context(32x1024), weights(32x2048)]

    cudaFuncSetAttribute(energy_kernel,
                         cudaFuncAttributeMaxDynamicSharedMemorySize, DYN_SMEM);

    enc_to_half<<<4096, 256>>>(enc);
    hproj_kernel<<<128, 256>>>(hidden, attn_w, attn_b);
    energy_kernel<<<dim3(8, 512), 128, DYN_SMEM>>>(v_w);
    softmax_kernel<<<Bdim, 512>>>(mask, out);
    ctx_part_kernel<<<dim3(Bdim, 16), 256>>>(out + Bdim * DEC);
    ctx_reduce_kernel<<<128, 256>>>(out);
}

// round 16
// speedup vs baseline: 1.0563x; 1.0084x over previous
#include <cuda_runtime.h>
#include <cuda_fp16.h>
#include <math.h>
#include <stdint.h>

#define Bdim 32
#define Sdim 2048
#define ENC  1024
#define DEC  1024
#define WTOT 2048
#define NEGV (-1e10f)

// ---------------- scratch ---------------------------------------------------
__device__ uint4 g_encH4[(size_t)Bdim * Sdim * ENC / 8]; // enc as fp16 [m][k]
__device__ uint4 g_weH4[DEC * ENC / 8];                  // w_e as fp16 [n][k]
__device__ float g_hpb[Bdim * DEC];                      // h_proj + bias
__device__ float g_part[(size_t)Bdim * Sdim * 8];        // per-(m, ntile) partials
__device__ float g_ctx_part[32 * Bdim * ENC];            // split ctx partials (4MB)

// ---------------- helpers ----------------------------------------------------
__device__ __forceinline__ uint32_t smem_u32(const void* p) {
    uint32_t a;
    asm("{ .reg .u64 t; cvta.to.shared.u64 t, %1; cvt.u32.u64 %0, t; }"
        : "=r"(a) : "l"(p));
    return a;
}
__device__ __forceinline__ uint32_t h2pack(float x, float y) {
    __half2 h = __floats2half2_rn(x, y);
    return *(uint32_t*)&h;
}
__device__ __forceinline__ void mma_f16(float* d, uint32_t a0, uint32_t a1,
                                        uint32_t a2, uint32_t a3,
                                        uint32_t b0, uint32_t b1) {
    asm volatile(
        "mma.sync.aligned.m16n8k16.row.col.f32.f16.f16.f32 "
        "{%0,%1,%2,%3}, {%4,%5,%6,%7}, {%8,%9}, {%0,%1,%2,%3};"
        : "+f"(d[0]), "+f"(d[1]), "+f"(d[2]), "+f"(d[3])
        : "r"(a0), "r"(a1), "r"(a2), "r"(a3), "r"(b0), "r"(b1));
}
#define LDSM4(r0, r1, r2, r3, a) \
    asm volatile("ldmatrix.sync.aligned.m8n8.x4.shared.b16 {%0,%1,%2,%3}, [%4];" \
                 : "=r"(r0), "=r"(r1), "=r"(r2), "=r"(r3) : "r"(a))

// ---------------- prep: hproj (blocks 0..127, FIRST) + enc conversion -------
// hproj blocks launch first so their ~5us of FMA work hides inside the
// DRAM-bound conversion (blocks 128..4223). Conversion blocks keep >=7
// blocks/SM residency despite the 32KB static smem (DRAM-bound, insensitive).
__global__ __launch_bounds__(256) void prep_kernel(
    const float* __restrict__ enc,
    const float* __restrict__ hidden,
    const float* __restrict__ attn_w,
    const float* __restrict__ attn_b) {
    __shared__ float ws8[8 * DEC];              // 32 KB (hproj blocks only)
    int tid = threadIdx.x;

    if (blockIdx.x >= 128) {
        // enc fp32 -> fp16, grid-stride over 4096 conversion blocks
        size_t n8 = (size_t)Bdim * Sdim * ENC / 8;
        size_t stride = (size_t)4096 * 256;
        for (size_t i = (size_t)(blockIdx.x - 128) * 256 + tid; i < n8; i += stride) {
            float4 f0 = ((const float4*)enc)[2 * i];
            float4 f1 = ((const float4*)enc)[2 * i + 1];
            uint4 o;
            o.x = h2pack(f0.x, f0.y); o.y = h2pack(f0.z, f0.w);
            o.z = h2pack(f1.x, f1.y); o.w = h2pack(f1.z, f1.w);
            g_encH4[i] = o;
        }
        return;
    }

    // ---- hproj path (8 k-rows per block, coalesced) + w_e conversion ----
    int kb = blockIdx.x * 8;
#pragma unroll
    for (int t = 0; t < 8; ++t) {
        int u = t * 256 + tid;
        int r = u >> 8, c = u & 255;
        ((float4*)ws8)[r * 256 + c] =
            ((const float4*)(attn_w + (size_t)(kb + r) * WTOT))[c];
    }
#pragma unroll
    for (int t = 0; t < 4; ++t) {
        int u = t * 256 + tid;
        int r = u >> 7, c = u & 127;
        const float* src = attn_w + (size_t)(kb + r) * WTOT + DEC + c * 8;
        float4 f0 = ((const float4*)src)[0];
        float4 f1 = ((const float4*)src)[1];
        uint4 o;
        o.x = h2pack(f0.x, f0.y); o.y = h2pack(f0.z, f0.w);
        o.z = h2pack(f1.x, f1.y); o.w = h2pack(f1.z, f1.w);
        g_weH4[(kb + r) * 128 + c] = o;
    }
    __syncthreads();

    int b = tid >> 3, l = tid & 7;
    const float4* h4 = (const float4*)(hidden + (size_t)b * DEC);
    const float4* w4 = (const float4*)ws8;
    float p[8];
#pragma unroll
    for (int kk = 0; kk < 8; ++kk) p[kk] = 0.f;
    for (int j = l; j < 256; j += 8) {
        float4 hv = h4[j];
#pragma unroll
        for (int kk = 0; kk < 8; ++kk) {
            float4 wv = w4[kk * 256 + j];
            p[kk] += hv.x * wv.x + hv.y * wv.y + hv.z * wv.z + hv.w * wv.w;
        }
    }
#pragma unroll
    for (int kk = 0; kk < 8; ++kk) {
        p[kk] += __shfl_down_sync(0xffffffffu, p[kk], 4, 8);
        p[kk] += __shfl_down_sync(0xffffffffu, p[kk], 2, 8);
        p[kk] += __shfl_down_sync(0xffffffffu, p[kk], 1, 8);
    }
    if (l == 0) {
#pragma unroll
        for (int kk = 0; kk < 8; ++kk)
            g_hpb[b * DEC + kb + kk] = p[kk] + attn_b[kb + kk];
    }
}

// ---------------- energy GEMM: fp16 mma.sync, frag-pipelined (R9 best) ------
#define NCHUNK 32
#define A_STG_B 10240            // 128 rows * 80B
#define B_STG_B 10240
#define STG_B   (A_STG_B + B_STG_B)
#define NSTAGE  5
#define DYN_SMEM (NSTAGE * STG_B)

__device__ __forceinline__ void issue_chunk(uint32_t sbase, int stage, int chunk,
                                            int m0, int n0, int tid) {
    uint32_t sb = sbase + stage * STG_B;
    int k0 = chunk * 32;
    const __half* encH = (const __half*)g_encH4;
    const __half* weH  = (const __half*)g_weH4;
#pragma unroll
    for (int t = 0; t < 8; ++t) {
        int u = t * 128 + tid;                  // 16B units: A 512, B 512
        const __half* g;
        uint32_t so;
        if (u < 512) {
            int r = u >> 2, seg = u & 3;
            so = (uint32_t)(r * 80 + seg * 16);
            g = encH + (size_t)(m0 + r) * ENC + k0 + seg * 8;
        } else {
            int v = u - 512;
            int r = v >> 2, seg = v & 3;
            so = (uint32_t)(A_STG_B + r * 80 + seg * 16);
            g = weH + (size_t)(n0 + r) * ENC + k0 + seg * 8;
        }
        asm volatile("cp.async.cg.shared.global [%0], [%1], 16;"
                     :: "r"(sb + so), "l"(g));
    }
    asm volatile("cp.async.commit_group;" ::: "memory");
}

struct Frag { uint32_t r[4]; };
struct FragSet { Frag a[4]; Frag b[4]; };

__device__ __forceinline__ void load_frags(FragSet& f, uint32_t sb,
                                           uint32_t aBase, uint32_t bBase,
                                           uint32_t koff) {
#pragma unroll
    for (int p = 0; p < 4; ++p)
        LDSM4(f.a[p].r[0], f.a[p].r[1], f.a[p].r[2], f.a[p].r[3],
              sb + aBase + p * 1280 + koff);
#pragma unroll
    for (int p = 0; p < 4; ++p)
        LDSM4(f.b[p].r[0], f.b[p].r[1], f.b[p].r[2], f.b[p].r[3],
              sb + bBase + p * 1280 + koff);
}

__device__ __forceinline__ void mma_set(float acc[4][8][4], const FragSet& f) {
#pragma unroll
    for (int mi = 0; mi < 4; ++mi)
#pragma unroll
        for (int p = 0; p < 4; ++p) {
            mma_f16(acc[mi][2 * p],     f.a[mi].r[0], f.a[mi].r[1],
                    f.a[mi].r[2], f.a[mi].r[3], f.b[p].r[0], f.b[p].r[1]);
            mma_f16(acc[mi][2 * p + 1], f.a[mi].r[0], f.a[mi].r[1],
                    f.a[mi].r[2], f.a[mi].r[3], f.b[p].r[2], f.b[p].r[3]);
        }
}

__global__ void __launch_bounds__(128, 2) energy_kernel(const float* __restrict__ v_w) {
    extern __shared__ uint32_t sm[];
    __shared__ float red[128][2];
    uint32_t sbase = smem_u32(sm);

    int tid = threadIdx.x;
    int wid = tid >> 5, lane = tid & 31;
    int wm = wid >> 1, wn = wid & 1;            // 2x2 warp grid
    int ty = lane >> 2, tx = lane & 3;
    int nt = blockIdx.x, mt = blockIdx.y;
    int m0 = mt * 128, n0 = nt * 128;
    int bb = m0 >> 11;

    int aRow = wm * 64 + (lane & 7) + (((lane >> 3) & 1) << 3);
    uint32_t aBase = (uint32_t)(aRow * 80 + ((lane >> 4) << 4));
    int bRow = wn * 64 + (lane & 7) + ((lane >> 4) << 3);
    uint32_t bBase = (uint32_t)(A_STG_B + bRow * 80 + (((lane >> 3) & 1) << 4));

    float acc[4][8][4];
#pragma unroll
    for (int mi = 0; mi < 4; ++mi)
#pragma unroll
        for (int ni = 0; ni < 8; ++ni)
#pragma unroll
            for (int c = 0; c < 4; ++c) acc[mi][ni][c] = 0.f;

    issue_chunk(sbase, 0, 0, m0, n0, tid);
    issue_chunk(sbase, 1, 1, m0, n0, tid);
    issue_chunk(sbase, 2, 2, m0, n0, tid);
    issue_chunk(sbase, 3, 3, m0, n0, tid);

    FragSet cur, nxt;
    asm volatile("cp.async.wait_group 3;" ::: "memory");
    __syncthreads();
    load_frags(cur, sbase, aBase, bBase, 0);

    for (int i = 0; i < NCHUNK; ++i) {
        if (i < 29)      asm volatile("cp.async.wait_group 2;" ::: "memory");
        else if (i == 29) asm volatile("cp.async.wait_group 1;" ::: "memory");
        else              asm volatile("cp.async.wait_group 0;" ::: "memory");
        __syncthreads();
        if (i + 4 < NCHUNK)
            issue_chunk(sbase, (i + 4) % NSTAGE, i + 4, m0, n0, tid);

        uint32_t sb  = sbase + (i % NSTAGE) * STG_B;
        uint32_t sbn = sbase + ((i + 1) % NSTAGE) * STG_B;

        load_frags(nxt, sb, aBase, bBase, 32);
        mma_set(acc, cur);
        if (i + 1 < NCHUNK) load_frags(cur, sbn, aBase, bBase, 0);
        mma_set(acc, nxt);
    }

    // Epilogue: tanh + v_w partial reduction over this block's 128 cols.
    int colbase = n0 + wn * 64 + tx * 2;
    int hb = bb * DEC;
    float pr[4][2];
#pragma unroll
    for (int mi = 0; mi < 4; ++mi) { pr[mi][0] = 0.f; pr[mi][1] = 0.f; }
#pragma unroll
    for (int ni = 0; ni < 8; ++ni) {
        int c0 = colbase + ni * 8;
        float hp0 = g_hpb[hb + c0],  hp1 = g_hpb[hb + c0 + 1];
        float vw0 = v_w[c0],         vw1 = v_w[c0 + 1];
#pragma unroll
        for (int mi = 0; mi < 4; ++mi) {
            pr[mi][0] += tanhf(acc[mi][ni][0] + hp0) * vw0
                       + tanhf(acc[mi][ni][1] + hp1) * vw1;
            pr[mi][1] += tanhf(acc[mi][ni][2] + hp0) * vw0
                       + tanhf(acc[mi][ni][3] + hp1) * vw1;
        }
    }
#pragma unroll
    for (int mi = 0; mi < 4; ++mi)
#pragma unroll
        for (int h = 0; h < 2; ++h) {
            float p = pr[mi][h];
            p += __shfl_xor_sync(0xffffffffu, p, 1);
            p += __shfl_xor_sync(0xffffffffu, p, 2);
            if (tx == 0) red[wm * 64 + mi * 16 + h * 8 + ty][wn] = p;
        }
    __syncthreads();
    g_part[((size_t)(m0 + tid)) * 8 + nt] = red[tid][0] + red[tid][1];
}

// ---------------- masked softmax (512 threads, sums 8 partials) -------------
__global__ void softmax_kernel(const int* __restrict__ mask, float* __restrict__ out) {
    int b = blockIdx.x;
    __shared__ float sh[Sdim];
    __shared__ float wr[16];
    int tid = threadIdx.x;  // 512

    float lmax = -1e30f;
    for (int s = tid; s < Sdim; s += 512) {
        float v;
        if (mask[b * Sdim + s] == 0) v = NEGV;
        else {
            const float4* pp = (const float4*)(g_part + ((size_t)(b * Sdim + s)) * 8);
            float4 p0 = pp[0], p1 = pp[1];
            v = ((p0.x + p0.y) + (p0.z + p0.w)) + ((p1.x + p1.y) + (p1.z + p1.w));
        }
        sh[s] = v;
        lmax = fmaxf(lmax, v);
    }
#pragma unroll
    for (int o = 16; o; o >>= 1) lmax = fmaxf(lmax, __shfl_xor_sync(~0u, lmax, o));
    if ((tid & 31) == 0) wr[tid >> 5] = lmax;
    __syncthreads();
    if (tid < 32) {
        float v = (tid < 16) ? wr[tid] : -1e30f;
#pragma unroll
        for (int o = 8; o; o >>= 1) v = fmaxf(v, __shfl_xor_sync(~0u, v, o));
        if (tid == 0) wr[0] = v;
    }
    __syncthreads();
    float gmax = wr[0];

    float lsum = 0.f;
    for (int s = tid; s < Sdim; s += 512) {
        float e = expf(sh[s] - gmax);
        sh[s] = e;
        lsum += e;
    }
    __syncthreads();
#pragma unroll
    for (int o = 16; o; o >>= 1) lsum += __shfl_xor_sync(~0u, lsum, o);
    if ((tid & 31) == 0) wr[tid >> 5] = lsum;
    __syncthreads();
    if (tid < 32) {
        float v = (tid < 16) ? wr[tid] : 0.f;
#pragma unroll
        for (int o = 8; o; o >>= 1) v += __shfl_xor_sync(~0u, v, o);
        if (tid == 0) wr[0] = v;
    }
    __syncthreads();
    float inv = 1.f / wr[0];
    float* w = out + Bdim * DEC;
    for (int s = tid; s < Sdim; s += 512) w[b * Sdim + s] = sh[s] * inv;
}

// ---------------- context: uint4 loads, 512 blocks, parity split ------------
__global__ __launch_bounds__(256) void ctx_part_kernel(const float* __restrict__ w) {
    int seg = threadIdx.x & 127;
    int parity = threadIdx.x >> 7;
    int b = blockIdx.x, z = blockIdx.y;
    const uint4* ep = g_encH4 + ((size_t)b * Sdim + z * 128) * 128 + seg;
    const float* wp = w + b * Sdim + z * 128;

    float a0 = 0.f, a1 = 0.f, a2 = 0.f, a3 = 0.f;
    float a4 = 0.f, a5 = 0.f, a6 = 0.f, a7 = 0.f;
    for (int s0 = 0; s0 < 128; s0 += 16) {
#pragma unroll
        for (int u = 0; u < 8; ++u) {
            int r = s0 + u * 2 + parity;
            uint4 v = ep[(size_t)r * 128];
            float wv = wp[r];
            float2 f0 = __half22float2(*(__half2*)&v.x);
            float2 f1 = __half22float2(*(__half2*)&v.y);
            float2 f2 = __half22float2(*(__half2*)&v.z);
            float2 f3 = __half22float2(*(__half2*)&v.w);
            a0 += wv * f0.x; a1 += wv * f0.y;
            a2 += wv * f1.x; a3 += wv * f1.y;
            a4 += wv * f2.x; a5 += wv * f2.y;
            a6 += wv * f3.x; a7 += wv * f3.y;
        }
    }
    int z2 = z * 2 + parity;
    float* dst = g_ctx_part + (((size_t)z2 * Bdim + b) << 10) + seg * 8;
    ((float4*)dst)[0] = make_float4(a0, a1, a2, a3);
    ((float4*)dst)[1] = make_float4(a4, a5, a6, a7);
}
__global__ void ctx_reduce_kernel(float* __restrict__ out) {
    int id = blockIdx.x * 256 + threadIdx.x;
    float s = 0.f;
#pragma unroll
    for (int z = 0; z < 32; ++z) s += g_ctx_part[(z << 15) + id];
    out[id] = s;
}

// ---------------------------------------------------------------------------
extern "C" void kernel_launch(void* const* d_in, const int* in_sizes, int n_in,
                              void* d_out, int out_size) {
    const float* hidden = (const float*)d_in[0];
    const float* enc    = (const float*)d_in[1];
    const int*   mask   = (const int*)d_in[2];
    const float* attn_w = (const float*)d_in[3];
    const float* attn_b = (const float*)d_in[4];
    const float* v_w    = (const float*)d_in[5];
    float* out = (float*)d_out;   // [context(32x1024), weights(32x2048)]

    cudaFuncSetAttribute(energy_kernel,
                         cudaFuncAttributeMaxDynamicSharedMemorySize, DYN_SMEM);

    prep_kernel<<<4224, 256>>>(enc, hidden, attn_w, attn_b);
    energy_kernel<<<dim3(8, 512), 128, DYN_SMEM>>>(v_w);
    softmax_kernel<<<Bdim, 512>>>(mask, out);
    ctx_part_kernel<<<dim3(Bdim, 16), 256>>>(out + Bdim * DEC);
    ctx_reduce_kernel<<<128, 256>>>(out);
}

// round 17
// speedup vs baseline: 1.0677x; 1.0107x over previous
#include <cuda_runtime.h>
#include <cuda_fp16.h>
#include <math.h>
#include <stdint.h>

#define Bdim 32
#define Sdim 2048
#define ENC  1024
#define DEC  1024
#define WTOT 2048
#define NEGV (-1e10f)

// ---------------- scratch ---------------------------------------------------
__device__ uint4 g_encH4[(size_t)Bdim * Sdim * ENC / 8]; // enc as fp16 [m][k]
__device__ uint4 g_weH4[DEC * ENC / 8];                  // w_e as fp16 [n][k]
__device__ float g_hpb[Bdim * DEC];                      // h_proj + bias
__device__ float g_part[(size_t)Bdim * Sdim * 8];        // per-(m, ntile) partials
__device__ float g_ctx_part[64 * Bdim * ENC];            // split ctx partials (8MB)

// ---------------- helpers ----------------------------------------------------
__device__ __forceinline__ uint32_t smem_u32(const void* p) {
    uint32_t a;
    asm("{ .reg .u64 t; cvta.to.shared.u64 t, %1; cvt.u32.u64 %0, t; }"
        : "=r"(a) : "l"(p));
    return a;
}
__device__ __forceinline__ uint32_t h2pack(float x, float y) {
    __half2 h = __floats2half2_rn(x, y);
    return *(uint32_t*)&h;
}
__device__ __forceinline__ void mma_f16(float* d, uint32_t a0, uint32_t a1,
                                        uint32_t a2, uint32_t a3,
                                        uint32_t b0, uint32_t b1) {
    asm volatile(
        "mma.sync.aligned.m16n8k16.row.col.f32.f16.f16.f32 "
        "{%0,%1,%2,%3}, {%4,%5,%6,%7}, {%8,%9}, {%0,%1,%2,%3};"
        : "+f"(d[0]), "+f"(d[1]), "+f"(d[2]), "+f"(d[3])
        : "r"(a0), "r"(a1), "r"(a2), "r"(a3), "r"(b0), "r"(b1));
}
#define LDSM4(r0, r1, r2, r3, a) \
    asm volatile("ldmatrix.sync.aligned.m8n8.x4.shared.b16 {%0,%1,%2,%3}, [%4];" \
                 : "=r"(r0), "=r"(r1), "=r"(r2), "=r"(r3) : "r"(a))

// ---------------- prep: hproj (blocks 0..127, FIRST) + enc conversion -------
__global__ __launch_bounds__(256) void prep_kernel(
    const float* __restrict__ enc,
    const float* __restrict__ hidden,
    const float* __restrict__ attn_w,
    const float* __restrict__ attn_b) {
    __shared__ float ws8[8 * DEC];              // 32 KB (hproj blocks only)
    int tid = threadIdx.x;

    if (blockIdx.x >= 128) {
        size_t n8 = (size_t)Bdim * Sdim * ENC / 8;
        size_t stride = (size_t)4096 * 256;
        for (size_t i = (size_t)(blockIdx.x - 128) * 256 + tid; i < n8; i += stride) {
            float4 f0 = ((const float4*)enc)[2 * i];
            float4 f1 = ((const float4*)enc)[2 * i + 1];
            uint4 o;
            o.x = h2pack(f0.x, f0.y); o.y = h2pack(f0.z, f0.w);
            o.z = h2pack(f1.x, f1.y); o.w = h2pack(f1.z, f1.w);
            g_encH4[i] = o;
        }
        return;
    }

    int kb = blockIdx.x * 8;
#pragma unroll
    for (int t = 0; t < 8; ++t) {
        int u = t * 256 + tid;
        int r = u >> 8, c = u & 255;
        ((float4*)ws8)[r * 256 + c] =
            ((const float4*)(attn_w + (size_t)(kb + r) * WTOT))[c];
    }
#pragma unroll
    for (int t = 0; t < 4; ++t) {
        int u = t * 256 + tid;
        int r = u >> 7, c = u & 127;
        const float* src = attn_w + (size_t)(kb + r) * WTOT + DEC + c * 8;
        float4 f0 = ((const float4*)src)[0];
        float4 f1 = ((const float4*)src)[1];
        uint4 o;
        o.x = h2pack(f0.x, f0.y); o.y = h2pack(f0.z, f0.w);
        o.z = h2pack(f1.x, f1.y); o.w = h2pack(f1.z, f1.w);
        g_weH4[(kb + r) * 128 + c] = o;
    }
    __syncthreads();

    int b = tid >> 3, l = tid & 7;
    const float4* h4 = (const float4*)(hidden + (size_t)b * DEC);
    const float4* w4 = (const float4*)ws8;
    float p[8];
#pragma unroll
    for (int kk = 0; kk < 8; ++kk) p[kk] = 0.f;
    for (int j = l; j < 256; j += 8) {
        float4 hv = h4[j];
#pragma unroll
        for (int kk = 0; kk < 8; ++kk) {
            float4 wv = w4[kk * 256 + j];
            p[kk] += hv.x * wv.x + hv.y * wv.y + hv.z * wv.z + hv.w * wv.w;
        }
    }
#pragma unroll
    for (int kk = 0; kk < 8; ++kk) {
        p[kk] += __shfl_down_sync(0xffffffffu, p[kk], 4, 8);
        p[kk] += __shfl_down_sync(0xffffffffu, p[kk], 2, 8);
        p[kk] += __shfl_down_sync(0xffffffffu, p[kk], 1, 8);
    }
    if (l == 0) {
#pragma unroll
        for (int kk = 0; kk < 8; ++kk)
            g_hpb[b * DEC + kb + kk] = p[kk] + attn_b[kb + kk];
    }
}

// ---------------- energy GEMM: fp16 mma.sync, frag-pipelined (R9 best) ------
#define NCHUNK 32
#define A_STG_B 10240            // 128 rows * 80B
#define B_STG_B 10240
#define STG_B   (A_STG_B + B_STG_B)
#define NSTAGE  5
#define DYN_SMEM (NSTAGE * STG_B)

__device__ __forceinline__ void issue_chunk(uint32_t sbase, int stage, int chunk,
                                            int m0, int n0, int tid) {
    uint32_t sb = sbase + stage * STG_B;
    int k0 = chunk * 32;
    const __half* encH = (const __half*)g_encH4;
    const __half* weH  = (const __half*)g_weH4;
#pragma unroll
    for (int t = 0; t < 8; ++t) {
        int u = t * 128 + tid;                  // 16B units: A 512, B 512
        const __half* g;
        uint32_t so;
        if (u < 512) {
            int r = u >> 2, seg = u & 3;
            so = (uint32_t)(r * 80 + seg * 16);
            g = encH + (size_t)(m0 + r) * ENC + k0 + seg * 8;
        } else {
            int v = u - 512;
            int r = v >> 2, seg = v & 3;
            so = (uint32_t)(A_STG_B + r * 80 + seg * 16);
            g = weH + (size_t)(n0 + r) * ENC + k0 + seg * 8;
        }
        asm volatile("cp.async.cg.shared.global [%0], [%1], 16;"
                     :: "r"(sb + so), "l"(g));
    }
    asm volatile("cp.async.commit_group;" ::: "memory");
}

struct Frag { uint32_t r[4]; };
struct FragSet { Frag a[4]; Frag b[4]; };

__device__ __forceinline__ void load_frags(FragSet& f, uint32_t sb,
                                           uint32_t aBase, uint32_t bBase,
                                           uint32_t koff) {
#pragma unroll
    for (int p = 0; p < 4; ++p)
        LDSM4(f.a[p].r[0], f.a[p].r[1], f.a[p].r[2], f.a[p].r[3],
              sb + aBase + p * 1280 + koff);
#pragma unroll
    for (int p = 0; p < 4; ++p)
        LDSM4(f.b[p].r[0], f.b[p].r[1], f.b[p].r[2], f.b[p].r[3],
              sb + bBase + p * 1280 + koff);
}

__device__ __forceinline__ void mma_set(float acc[4][8][4], const FragSet& f) {
#pragma unroll
    for (int mi = 0; mi < 4; ++mi)
#pragma unroll
        for (int p = 0; p < 4; ++p) {
            mma_f16(acc[mi][2 * p],     f.a[mi].r[0], f.a[mi].r[1],
                    f.a[mi].r[2], f.a[mi].r[3], f.b[p].r[0], f.b[p].r[1]);
            mma_f16(acc[mi][2 * p + 1], f.a[mi].r[0], f.a[mi].r[1],
                    f.a[mi].r[2], f.a[mi].r[3], f.b[p].r[2], f.b[p].r[3]);
        }
}

__global__ void __launch_bounds__(128, 2) energy_kernel(const float* __restrict__ v_w) {
    extern __shared__ uint32_t sm[];
    __shared__ float red[128][2];
    uint32_t sbase = smem_u32(sm);

    int tid = threadIdx.x;
    int wid = tid >> 5, lane = tid & 31;
    int wm = wid >> 1, wn = wid & 1;            // 2x2 warp grid
    int ty = lane >> 2, tx = lane & 3;
    int nt = blockIdx.x, mt = blockIdx.y;
    int m0 = mt * 128, n0 = nt * 128;
    int bb = m0 >> 11;

    int aRow = wm * 64 + (lane & 7) + (((lane >> 3) & 1) << 3);
    uint32_t aBase = (uint32_t)(aRow * 80 + ((lane >> 4) << 4));
    int bRow = wn * 64 + (lane & 7) + ((lane >> 4) << 3);
    uint32_t bBase = (uint32_t)(A_STG_B + bRow * 80 + (((lane >> 3) & 1) << 4));

    float acc[4][8][4];
#pragma unroll
    for (int mi = 0; mi < 4; ++mi)
#pragma unroll
        for (int ni = 0; ni < 8; ++ni)
#pragma unroll
            for (int c = 0; c < 4; ++c) acc[mi][ni][c] = 0.f;

    issue_chunk(sbase, 0, 0, m0, n0, tid);
    issue_chunk(sbase, 1, 1, m0, n0, tid);
    issue_chunk(sbase, 2, 2, m0, n0, tid);
    issue_chunk(sbase, 3, 3, m0, n0, tid);

    FragSet cur, nxt;
    asm volatile("cp.async.wait_group 3;" ::: "memory");
    __syncthreads();
    load_frags(cur, sbase, aBase, bBase, 0);

    for (int i = 0; i < NCHUNK; ++i) {
        if (i < 29)      asm volatile("cp.async.wait_group 2;" ::: "memory");
        else if (i == 29) asm volatile("cp.async.wait_group 1;" ::: "memory");
        else              asm volatile("cp.async.wait_group 0;" ::: "memory");
        __syncthreads();
        if (i + 4 < NCHUNK)
            issue_chunk(sbase, (i + 4) % NSTAGE, i + 4, m0, n0, tid);

        uint32_t sb  = sbase + (i % NSTAGE) * STG_B;
        uint32_t sbn = sbase + ((i + 1) % NSTAGE) * STG_B;

        load_frags(nxt, sb, aBase, bBase, 32);
        mma_set(acc, cur);
        if (i + 1 < NCHUNK) load_frags(cur, sbn, aBase, bBase, 0);
        mma_set(acc, nxt);
    }

    // Epilogue: tanh + v_w partial reduction over this block's 128 cols.
    int colbase = n0 + wn * 64 + tx * 2;
    int hb = bb * DEC;
    float pr[4][2];
#pragma unroll
    for (int mi = 0; mi < 4; ++mi) { pr[mi][0] = 0.f; pr[mi][1] = 0.f; }
#pragma unroll
    for (int ni = 0; ni < 8; ++ni) {
        int c0 = colbase + ni * 8;
        float hp0 = g_hpb[hb + c0],  hp1 = g_hpb[hb + c0 + 1];
        float vw0 = v_w[c0],         vw1 = v_w[c0 + 1];
#pragma unroll
        for (int mi = 0; mi < 4; ++mi) {
            pr[mi][0] += tanhf(acc[mi][ni][0] + hp0) * vw0
                       + tanhf(acc[mi][ni][1] + hp1) * vw1;
            pr[mi][1] += tanhf(acc[mi][ni][2] + hp0) * vw0
                       + tanhf(acc[mi][ni][3] + hp1) * vw1;
        }
    }
#pragma unroll
    for (int mi = 0; mi < 4; ++mi)
#pragma unroll
        for (int h = 0; h < 2; ++h) {
            float p = pr[mi][h];
            p += __shfl_xor_sync(0xffffffffu, p, 1);
            p += __shfl_xor_sync(0xffffffffu, p, 2);
            if (tx == 0) red[wm * 64 + mi * 16 + h * 8 + ty][wn] = p;
        }
    __syncthreads();
    g_part[((size_t)(m0 + tid)) * 8 + nt] = red[tid][0] + red[tid][1];
}

// ---------------- masked softmax (512 threads, sums 8 partials) -------------
__global__ void softmax_kernel(const int* __restrict__ mask, float* __restrict__ out) {
    int b = blockIdx.x;
    __shared__ float sh[Sdim];
    __shared__ float wr[16];
    int tid = threadIdx.x;  // 512

    float lmax = -1e30f;
    for (int s = tid; s < Sdim; s += 512) {
        float v;
        if (mask[b * Sdim + s] == 0) v = NEGV;
        else {
            const float4* pp = (const float4*)(g_part + ((size_t)(b * Sdim + s)) * 8);
            float4 p0 = pp[0], p1 = pp[1];
            v = ((p0.x + p0.y) + (p0.z + p0.w)) + ((p1.x + p1.y) + (p1.z + p1.w));
        }
        sh[s] = v;
        lmax = fmaxf(lmax, v);
    }
#pragma unroll
    for (int o = 16; o; o >>= 1) lmax = fmaxf(lmax, __shfl_xor_sync(~0u, lmax, o));
    if ((tid & 31) == 0) wr[tid >> 5] = lmax;
    __syncthreads();
    if (tid < 32) {
        float v = (tid < 16) ? wr[tid] : -1e30f;
#pragma unroll
        for (int o = 8; o; o >>= 1) v = fmaxf(v, __shfl_xor_sync(~0u, v, o));
        if (tid == 0) wr[0] = v;
    }
    __syncthreads();
    float gmax = wr[0];

    float lsum = 0.f;
    for (int s = tid; s < Sdim; s += 512) {
        float e = expf(sh[s] - gmax);
        sh[s] = e;
        lsum += e;
    }
    __syncthreads();
#pragma unroll
    for (int o = 16; o; o >>= 1) lsum += __shfl_xor_sync(~0u, lsum, o);
    if ((tid & 31) == 0) wr[tid >> 5] = lsum;
    __syncthreads();
    if (tid < 32) {
        float v = (tid < 16) ? wr[tid] : 0.f;
#pragma unroll
        for (int o = 8; o; o >>= 1) v += __shfl_xor_sync(~0u, v, o);
        if (tid == 0) wr[0] = v;
    }
    __syncthreads();
    float inv = 1.f / wr[0];
    float* w = out + Bdim * DEC;
    for (int s = tid; s < Sdim; s += 512) w[b * Sdim + s] = sh[s] * inv;
}

// ---------------- context: uint4 loads, 1024 blocks, parity split -----------
// grid (Bdim, 32), 256 threads. z-slice = 64 rows; seg = tid&127 owns one
// uint4 (8 halves) per row; parity = tid>>7 streams 32 parity-interleaved
// rows. Partials land in z2 = 2z+parity (64 slots); reduce sums 64.
__global__ __launch_bounds__(256) void ctx_part_kernel(const float* __restrict__ w) {
    int seg = threadIdx.x & 127;
    int parity = threadIdx.x >> 7;
    int b = blockIdx.x, z = blockIdx.y;
    const uint4* ep = g_encH4 + ((size_t)b * Sdim + z * 64) * 128 + seg;
    const float* wp = w + b * Sdim + z * 64;

    float a0 = 0.f, a1 = 0.f, a2 = 0.f, a3 = 0.f;
    float a4 = 0.f, a5 = 0.f, a6 = 0.f, a7 = 0.f;
    for (int s0 = 0; s0 < 64; s0 += 16) {
#pragma unroll
        for (int u = 0; u < 8; ++u) {
            int r = s0 + u * 2 + parity;
            uint4 v = ep[(size_t)r * 128];
            float wv = wp[r];
            float2 f0 = __half22float2(*(__half2*)&v.x);
            float2 f1 = __half22float2(*(__half2*)&v.y);
            float2 f2 = __half22float2(*(__half2*)&v.z);
            float2 f3 = __half22float2(*(__half2*)&v.w);
            a0 += wv * f0.x; a1 += wv * f0.y;
            a2 += wv * f1.x; a3 += wv * f1.y;
            a4 += wv * f2.x; a5 += wv * f2.y;
            a6 += wv * f3.x; a7 += wv * f3.y;
        }
    }
    int z2 = z * 2 + parity;
    float* dst = g_ctx_part + (((size_t)z2 * Bdim + b) << 10) + seg * 8;
    ((float4*)dst)[0] = make_float4(a0, a1, a2, a3);
    ((float4*)dst)[1] = make_float4(a4, a5, a6, a7);
}
__global__ void ctx_reduce_kernel(float* __restrict__ out) {
    int id = blockIdx.x * 256 + threadIdx.x;
    float s = 0.f;
#pragma unroll
    for (int z = 0; z < 64; ++z) s += g_ctx_part[(z << 15) + id];
    out[id] = s;
}

// ---------------------------------------------------------------------------
extern "C" void kernel_launch(void* const* d_in, const int* in_sizes, int n_in,
                              void* d_out, int out_size) {
    const float* hidden = (const float*)d_in[0];
    const float* enc    = (const float*)d_in[1];
    const int*   mask   = (const int*)d_in[2];
    const float* attn_w = (const float*)d_in[3];
    const float* attn_b = (const float*)d_in[4];
    const float* v_w    = (const float*)d_in[5];
    float* out = (float*)d_out;   // [context(32x1024), weights(32x2048)]

    cudaFuncSetAttribute(energy_kernel,
                         cudaFuncAttributeMaxDynamicSharedMemorySize, DYN_SMEM);

    prep_kernel<<<4224, 256>>>(enc, hidden, attn_w, attn_b);
    energy_kernel<<<dim3(8, 512), 128, DYN_SMEM>>>(v_w);
    softmax_kernel<<<Bdim, 512>>>(mask, out);
    ctx_part_kernel<<<dim3(Bdim, 32), 256>>>(out + Bdim * DEC);
    ctx_reduce_kernel<<<128, 256>>>(out);
}